// round 6
// baseline (speedup 1.0000x reference)
#include <cuda_runtime.h>
#include <math.h>
#include <stdint.h>

// ---------------------------------------------------------------------------
// MambaEncoderLayer: LN -> bidirectional Mamba -> residual -> LN -> FC(GELU) -> residual
// B=2, L=1024, D_MODEL=768, D_INNER=1536, D_STATE=16, D_CONV=4, DT_RANK=48
// ---------------------------------------------------------------------------

constexpr int B_  = 2;
constexpr int L_  = 1024;
constexpr int DM  = 768;
constexpr int DI  = 1536;
constexpr int DS  = 16;
constexpr int DTR = 48;
constexpr int M_  = B_ * L_;      // 2048 rows
constexpr int XLD = 128;          // padded x_dbl leading dim (80 -> 128)

// Scratch (static device globals: no allocation anywhere)
__device__ float g_xn   [M_ * DM];
__device__ float g_xnrev[M_ * DM];
__device__ float g_xz   [M_ * 2 * DI];   // in_proj out: [xc | z]
__device__ float g_xc   [M_ * DI];       // conv+silu out
__device__ float g_xdbl [M_ * XLD];      // x_proj out (padded to 128 cols)
__device__ float g_dt   [M_ * DI];       // softplus(dt)
__device__ float g_yg   [M_ * DI];       // scan output, gated
__device__ float g_yf   [M_ * DM];
__device__ float g_yb   [M_ * DM];
__device__ float g_x2   [M_ * DM];
__device__ float g_xn2  [M_ * DM];
__device__ float g_wxp  [XLD * DI];      // zero-padded x_proj weight

// ---------------------------------------------------------------------------
// LayerNorm over last dim (768). One block per row, 256 threads x 3 elems.
// Optionally also writes the L-flipped copy (for the backward Mamba branch).
// ---------------------------------------------------------------------------
__global__ void ln_kernel(const float* __restrict__ x,
                          const float* __restrict__ w,
                          const float* __restrict__ bb,
                          float* __restrict__ out,
                          float* __restrict__ outrev)
{
    int row = blockIdx.x;
    int t   = threadIdx.x;
    const float* xr = x + (size_t)row * DM;
    float v0 = xr[t], v1 = xr[t + 256], v2 = xr[t + 512];
    float s = v0 + v1 + v2;
    float q = v0 * v0 + v1 * v1 + v2 * v2;
    #pragma unroll
    for (int o = 16; o > 0; o >>= 1) {
        s += __shfl_xor_sync(0xffffffffu, s, o);
        q += __shfl_xor_sync(0xffffffffu, q, o);
    }
    __shared__ float ss[8], sq[8];
    int wid = t >> 5, lid = t & 31;
    if (lid == 0) { ss[wid] = s; sq[wid] = q; }
    __syncthreads();
    if (wid == 0) {
        s = ss[lid & 7]; q = sq[lid & 7];
        #pragma unroll
        for (int o = 4; o > 0; o >>= 1) {
            s += __shfl_xor_sync(0xffffffffu, s, o);
            q += __shfl_xor_sync(0xffffffffu, q, o);
        }
        if (lid == 0) { ss[0] = s; sq[0] = q; }
    }
    __syncthreads();
    s = ss[0]; q = sq[0];
    float mean = s * (1.0f / DM);
    float var  = q * (1.0f / DM) - mean * mean;
    float rstd = rsqrtf(var + 1e-5f);

    int b = row >> 10, l = row & (L_ - 1);
    size_t rbase = (size_t)row * DM;
    size_t rrev  = (size_t)(b * L_ + (L_ - 1 - l)) * DM;
    float vv[3] = { v0, v1, v2 };
    #pragma unroll
    for (int i = 0; i < 3; i++) {
        int j = t + i * 256;
        float o = (vv[i] - mean) * rstd * w[j] + bb[j];
        out[rbase + j] = o;
        if (outrev) outrev[rrev + j] = o;
    }
}

// ---------------------------------------------------------------------------
// Generic tiled SGEMM: C[M,N] = epi( A[M,K](lda) @ W[N,K]^T )
// Requires: M%BM==0, N%BN==0, K%BK==0, lda%4==0, K%4==0, BK%4==0.
// ---------------------------------------------------------------------------
enum { EPI_NONE = 0, EPI_SOFTPLUS = 1, EPI_GELU_RES = 2 };

template <int BM, int BN, int BK, int TM, int TN, int EPI>
__global__ __launch_bounds__((BM / TM) * (BN / TN))
void sgemm(int Mm, int Nn, int K, int lda,
           const float* __restrict__ A,
           const float* __restrict__ W,
           const float* __restrict__ bias,
           const float* __restrict__ res,
           float* __restrict__ C)
{
    constexpr int NT = (BM / TM) * (BN / TN);
    static_assert(NT == 256, "256 threads expected");
    __shared__ float As[BK][BM];
    __shared__ float Bs[BK][BN];

    int tid  = threadIdx.x;
    int crow = blockIdx.y * BM;
    int ccol = blockIdx.x * BN;
    int tr   = (tid / (BN / TN)) * TM;
    int tc   = (tid % (BN / TN)) * TN;

    float acc[TM][TN];
    #pragma unroll
    for (int i = 0; i < TM; i++)
        #pragma unroll
        for (int j = 0; j < TN; j++) acc[i][j] = 0.f;

    const float* Ab = A + (size_t)crow * lda;
    const float* Wb = W + (size_t)ccol * K;

    for (int k0 = 0; k0 < K; k0 += BK) {
        #pragma unroll
        for (int i = tid * 4; i < BM * BK; i += NT * 4) {
            int r = i / BK, c = i % BK;
            float4 v = *(const float4*)(Ab + (size_t)r * lda + k0 + c);
            As[c + 0][r] = v.x; As[c + 1][r] = v.y;
            As[c + 2][r] = v.z; As[c + 3][r] = v.w;
        }
        #pragma unroll
        for (int i = tid * 4; i < BN * BK; i += NT * 4) {
            int r = i / BK, c = i % BK;
            float4 v = *(const float4*)(Wb + (size_t)r * K + k0 + c);
            Bs[c + 0][r] = v.x; Bs[c + 1][r] = v.y;
            Bs[c + 2][r] = v.z; Bs[c + 3][r] = v.w;
        }
        __syncthreads();
        #pragma unroll
        for (int k = 0; k < BK; k++) {
            float ra[TM], rb[TN];
            #pragma unroll
            for (int i = 0; i < TM; i++) ra[i] = As[k][tr + i];
            #pragma unroll
            for (int j = 0; j < TN; j++) rb[j] = Bs[k][tc + j];
            #pragma unroll
            for (int i = 0; i < TM; i++)
                #pragma unroll
                for (int j = 0; j < TN; j++)
                    acc[i][j] = fmaf(ra[i], rb[j], acc[i][j]);
        }
        __syncthreads();
    }

    #pragma unroll
    for (int i = 0; i < TM; i++) {
        size_t rowo = (size_t)(crow + tr + i) * Nn;
        #pragma unroll
        for (int j = 0; j < TN; j++) {
            int n = ccol + tc + j;
            float v = acc[i][j];
            if (EPI == EPI_SOFTPLUS) {
                v += bias[n];
                v = (v > 20.f) ? v : log1pf(__expf(v));
            } else if (EPI == EPI_GELU_RES) {
                v += bias[n];
                float g = 0.5f * v * (1.f + erff(v * 0.70710678118654752f));
                v = g + res[rowo + n];
            }
            C[rowo + n] = v;
        }
    }
}

// ---------------------------------------------------------------------------
// Depthwise causal conv (D_CONV=4) + bias + SiLU.
// Input is the first DI columns of g_xz (row stride 2*DI).
// ---------------------------------------------------------------------------
__global__ void conv_silu(const float* __restrict__ xz,
                          const float* __restrict__ cw,
                          const float* __restrict__ cb,
                          float* __restrict__ xc)
{
    int idx = blockIdx.x * 256 + threadIdx.x;
    if (idx >= M_ * DI) return;
    int d  = idx % DI;
    int ml = idx / DI;
    int l  = ml & (L_ - 1);
    const float* base = xz + (size_t)ml * (2 * DI) + d;
    float w0 = cw[d * 4 + 0], w1 = cw[d * 4 + 1];
    float w2 = cw[d * 4 + 2], w3 = cw[d * 4 + 3];
    float acc = cb[d] + w3 * base[0];
    if (l >= 1) acc += w2 * base[-(ptrdiff_t)(2 * DI)];
    if (l >= 2) acc += w1 * base[-(ptrdiff_t)(4 * DI)];
    if (l >= 3) acc += w0 * base[-(ptrdiff_t)(6 * DI)];
    xc[idx] = acc / (1.f + __expf(-acc));   // silu
}

// Zero-pad x_proj weight from 80 rows to 128 rows (row length DI).
__global__ void pad_w(const float* __restrict__ xpw, float* __restrict__ wp)
{
    int idx = blockIdx.x * 256 + threadIdx.x;
    if (idx >= XLD * DI) return;
    int nrow = idx / DI;
    wp[idx] = (nrow < 80) ? xpw[idx] : 0.f;
}

// ---------------------------------------------------------------------------
// Selective scan. 16 lanes per channel (B*DI = 3072 channels, 2 per warp).
// h[n]_{l} = exp(dt*A[n]) * h[n]_{l-1} + dt*xc*B[l,n];  y_l = sum_n h[n]*C[l,n]
// then y = (y + xc*D) * silu(z)  written to yg.
// ---------------------------------------------------------------------------
__global__ void scan_kernel(const float* __restrict__ dt,
                            const float* __restrict__ xc,
                            const float* __restrict__ xdbl,
                            const float* __restrict__ xz,
                            const float* __restrict__ A_log,
                            const float* __restrict__ Dp,
                            float* __restrict__ yg)
{
    int w    = blockIdx.x * 8 + (threadIdx.x >> 5);
    int lane = threadIdx.x & 31;
    int c    = 2 * w + (lane >> 4);          // channel in [0, B*DI)
    int n    = lane & 15;                    // state index
    int b    = c / DI;
    int d    = c - b * DI;

    float An = -__expf(A_log[d * DS + n]);
    float Dv = Dp[d];
    float h  = 0.f;
    int base = b * L_;

    for (int l = 0; l < L_; l++) {
        int row = base + l;
        float dtv = __ldg(dt   + (size_t)row * DI  + d);
        float xcv = __ldg(xc   + (size_t)row * DI  + d);
        float Bv  = __ldg(xdbl + (size_t)row * XLD + 48 + n);
        float Cv  = __ldg(xdbl + (size_t)row * XLD + 64 + n);
        float dA  = __expf(dtv * An);
        h = fmaf(dA, h, dtv * xcv * Bv);
        float p = h * Cv;
        p += __shfl_xor_sync(0xffffffffu, p, 8);
        p += __shfl_xor_sync(0xffffffffu, p, 4);
        p += __shfl_xor_sync(0xffffffffu, p, 2);
        p += __shfl_xor_sync(0xffffffffu, p, 1);
        if (n == 0) {
            float y = p + xcv * Dv;
            float z = xz[(size_t)row * (2 * DI) + DI + d];
            y *= z / (1.f + __expf(-z));     // * silu(z)
            yg[(size_t)row * DI + d] = y;
        }
    }
}

// x2 = x + y_fwd + flip_L(y_bwd)
__global__ void combine_kernel(const float* __restrict__ x,
                               const float* __restrict__ yf,
                               const float* __restrict__ yb,
                               float* __restrict__ x2)
{
    int idx = blockIdx.x * 256 + threadIdx.x;
    if (idx >= M_ * DM) return;
    int j  = idx % DM;
    int ml = idx / DM;
    int l  = ml & (L_ - 1);
    int b  = ml >> 10;
    int mlr = (b << 10) + (L_ - 1 - l);
    x2[idx] = x[idx] + yf[idx] + yb[(size_t)mlr * DM + j];
}

// ---------------------------------------------------------------------------
// Launch
// ---------------------------------------------------------------------------
extern "C" void kernel_launch(void* const* d_in, const int* in_sizes, int n_in,
                              void* d_out, int out_size)
{
    const float* x    = (const float*)d_in[0];
    const float* ln1w = (const float*)d_in[1];
    const float* ln1b = (const float*)d_in[2];
    const float* ln2w = (const float*)d_in[3];
    const float* ln2b = (const float*)d_in[4];
    const float* fcw  = (const float*)d_in[5];
    const float* fcb  = (const float*)d_in[6];

    float *xn, *xnrev, *xz, *xcb, *xdbl, *dtb, *ygb, *yf, *yb, *x2, *xn2, *wp;
    cudaGetSymbolAddress((void**)&xn,    g_xn);
    cudaGetSymbolAddress((void**)&xnrev, g_xnrev);
    cudaGetSymbolAddress((void**)&xz,    g_xz);
    cudaGetSymbolAddress((void**)&xcb,   g_xc);
    cudaGetSymbolAddress((void**)&xdbl,  g_xdbl);
    cudaGetSymbolAddress((void**)&dtb,   g_dt);
    cudaGetSymbolAddress((void**)&ygb,   g_yg);
    cudaGetSymbolAddress((void**)&yf,    g_yf);
    cudaGetSymbolAddress((void**)&yb,    g_yb);
    cudaGetSymbolAddress((void**)&x2,    g_x2);
    cudaGetSymbolAddress((void**)&xn2,   g_xn2);
    cudaGetSymbolAddress((void**)&wp,    g_wxp);

    // 1) LN1 (also produces the L-flipped copy for the backward branch)
    ln_kernel<<<M_, 256>>>(x, ln1w, ln1b, xn, xnrev);

    for (int dir = 0; dir < 2; dir++) {
        const float* Ain  = dir ? xnrev : xn;
        int o = 7 + dir * 9;
        const float* ipw  = (const float*)d_in[o + 0];   // in_proj_w  (3072,768)
        const float* cw   = (const float*)d_in[o + 1];   // conv_w     (1536,4)
        const float* cb   = (const float*)d_in[o + 2];   // conv_b     (1536)
        const float* xpw  = (const float*)d_in[o + 3];   // x_proj_w   (80,1536)
        const float* dpw  = (const float*)d_in[o + 4];   // dt_proj_w  (1536,48)
        const float* dpb  = (const float*)d_in[o + 5];   // dt_proj_b  (1536)
        const float* alog = (const float*)d_in[o + 6];   // A_log      (1536,16)
        const float* Dpar = (const float*)d_in[o + 7];   // D          (1536)
        const float* opw  = (const float*)d_in[o + 8];   // out_proj_w (768,1536)
        float* ydir = dir ? yb : yf;

        // in_proj: xz = xn @ ipw^T   [2048 x 3072]
        sgemm<128, 128, 8, 8, 8, EPI_NONE>
            <<<dim3((2 * DI) / 128, M_ / 128), 256>>>(
                M_, 2 * DI, DM, DM, Ain, ipw, nullptr, nullptr, xz);

        // depthwise causal conv + bias + silu -> xc
        conv_silu<<<(M_ * DI + 255) / 256, 256>>>(xz, cw, cb, xcb);

        // pad x_proj weight to 128 rows, then x_dbl = xc @ wp^T [2048 x 128]
        pad_w<<<(XLD * DI + 255) / 256, 256>>>(xpw, wp);
        sgemm<64, 64, 16, 4, 4, EPI_NONE>
            <<<dim3(XLD / 64, M_ / 64), 256>>>(
                M_, XLD, DI, DI, xcb, wp, nullptr, nullptr, xdbl);

        // dt = softplus(x_dbl[:, :48] @ dpw^T + dpb)   [2048 x 1536]
        sgemm<128, 128, 8, 8, 8, EPI_SOFTPLUS>
            <<<dim3(DI / 128, M_ / 128), 256>>>(
                M_, DI, DTR, XLD, xdbl, dpw, dpb, nullptr, dtb);

        // selective scan + skip (xc*D) + gate silu(z)
        scan_kernel<<<192, 256>>>(dtb, xcb, xdbl, xz, alog, Dpar, ygb);

        // out_proj: ydir = yg @ opw^T  [2048 x 768]
        sgemm<64, 128, 16, 4, 8, EPI_NONE>
            <<<dim3(DM / 128, M_ / 64), 256>>>(
                M_, DM, DI, DI, ygb, opw, nullptr, nullptr, ydir);
    }

    // x2 = x + y_f + flip(y_b); LN2; out = gelu(LN2(x2) @ fcw^T + fcb) + x2
    combine_kernel<<<(M_ * DM + 255) / 256, 256>>>(x, yf, yb, x2);
    ln_kernel<<<M_, 256>>>(x2, ln2w, ln2b, xn2, nullptr);
    sgemm<64, 128, 16, 4, 8, EPI_GELU_RES>
        <<<dim3(DM / 128, M_ / 64), 256>>>(
            M_, DM, DM, DM, xn2, fcw, fcb, x2, (float*)d_out);
}

// round 7
// speedup vs baseline: 1.0051x; 1.0051x over previous
#include <cuda_runtime.h>
#include <math.h>
#include <stdint.h>

// ---------------------------------------------------------------------------
// MambaEncoderLayer: LN -> bidirectional Mamba -> residual -> LN -> FC(GELU) -> residual
// B=2, L=1024, D_MODEL=768, D_INNER=1536, D_STATE=16, D_CONV=4, DT_RANK=48
// ---------------------------------------------------------------------------

constexpr int B_  = 2;
constexpr int L_  = 1024;
constexpr int DM  = 768;
constexpr int DI  = 1536;
constexpr int DS  = 16;
constexpr int DTR = 48;
constexpr int M_  = B_ * L_;      // 2048 rows
constexpr int XLD = 128;          // padded x_dbl leading dim (80 -> 128)

// Scratch (static device globals: no allocation anywhere)
__device__ float g_xn   [M_ * DM];
__device__ float g_xnrev[M_ * DM];
__device__ float g_xz   [M_ * 2 * DI];   // in_proj out: [xc | z]
__device__ float g_xc   [M_ * DI];       // conv+silu out
__device__ float g_xdbl [M_ * XLD];      // x_proj out (padded to 128 cols)
__device__ float g_dt   [M_ * DI];       // softplus(dt)
__device__ float g_yg   [M_ * DI];       // scan output, gated
__device__ float g_yf   [M_ * DM];
__device__ float g_yb   [M_ * DM];
__device__ float g_x2   [M_ * DM];
__device__ float g_xn2  [M_ * DM];
__device__ float g_wxp  [XLD * DI];      // zero-padded x_proj weight

// ---------------------------------------------------------------------------
// LayerNorm over last dim (768). One block per row, 256 threads x 3 elems.
// Optionally also writes the L-flipped copy (for the backward Mamba branch).
// ---------------------------------------------------------------------------
__global__ void ln_kernel(const float* __restrict__ x,
                          const float* __restrict__ w,
                          const float* __restrict__ bb,
                          float* __restrict__ out,
                          float* __restrict__ outrev)
{
    int row = blockIdx.x;
    int t   = threadIdx.x;
    const float* xr = x + (size_t)row * DM;
    float v0 = xr[t], v1 = xr[t + 256], v2 = xr[t + 512];
    float s = v0 + v1 + v2;
    float q = v0 * v0 + v1 * v1 + v2 * v2;
    #pragma unroll
    for (int o = 16; o > 0; o >>= 1) {
        s += __shfl_xor_sync(0xffffffffu, s, o);
        q += __shfl_xor_sync(0xffffffffu, q, o);
    }
    __shared__ float ss[8], sq[8];
    int wid = t >> 5, lid = t & 31;
    if (lid == 0) { ss[wid] = s; sq[wid] = q; }
    __syncthreads();
    if (wid == 0) {
        s = ss[lid & 7]; q = sq[lid & 7];
        #pragma unroll
        for (int o = 4; o > 0; o >>= 1) {
            s += __shfl_xor_sync(0xffffffffu, s, o);
            q += __shfl_xor_sync(0xffffffffu, q, o);
        }
        if (lid == 0) { ss[0] = s; sq[0] = q; }
    }
    __syncthreads();
    s = ss[0]; q = sq[0];
    float mean = s * (1.0f / DM);
    float var  = q * (1.0f / DM) - mean * mean;
    float rstd = rsqrtf(var + 1e-5f);

    int b = row >> 10, l = row & (L_ - 1);
    size_t rbase = (size_t)row * DM;
    size_t rrev  = (size_t)(b * L_ + (L_ - 1 - l)) * DM;
    float vv[3] = { v0, v1, v2 };
    #pragma unroll
    for (int i = 0; i < 3; i++) {
        int j = t + i * 256;
        float o = (vv[i] - mean) * rstd * w[j] + bb[j];
        out[rbase + j] = o;
        if (outrev) outrev[rrev + j] = o;
    }
}

// ---------------------------------------------------------------------------
// Generic tiled SGEMM: C[M,N] = epi( A[M,K](lda) @ W[N,K]^T )
// Requires: M%BM==0, N%BN==0, K%BK==0, lda%4==0, K%4==0, BK%4==0.
// ---------------------------------------------------------------------------
enum { EPI_NONE = 0, EPI_SOFTPLUS = 1, EPI_GELU_RES = 2 };

template <int BM, int BN, int BK, int TM, int TN, int EPI>
__global__ __launch_bounds__((BM / TM) * (BN / TN))
void sgemm(int Mm, int Nn, int K, int lda,
           const float* __restrict__ A,
           const float* __restrict__ W,
           const float* __restrict__ bias,
           const float* __restrict__ res,
           float* __restrict__ C)
{
    constexpr int NT = (BM / TM) * (BN / TN);
    static_assert(NT == 256, "256 threads expected");
    __shared__ float As[BK][BM];
    __shared__ float Bs[BK][BN];

    int tid  = threadIdx.x;
    int crow = blockIdx.y * BM;
    int ccol = blockIdx.x * BN;
    int tr   = (tid / (BN / TN)) * TM;
    int tc   = (tid % (BN / TN)) * TN;

    float acc[TM][TN];
    #pragma unroll
    for (int i = 0; i < TM; i++)
        #pragma unroll
        for (int j = 0; j < TN; j++) acc[i][j] = 0.f;

    const float* Ab = A + (size_t)crow * lda;
    const float* Wb = W + (size_t)ccol * K;

    for (int k0 = 0; k0 < K; k0 += BK) {
        #pragma unroll
        for (int i = tid * 4; i < BM * BK; i += NT * 4) {
            int r = i / BK, c = i % BK;
            float4 v = *(const float4*)(Ab + (size_t)r * lda + k0 + c);
            As[c + 0][r] = v.x; As[c + 1][r] = v.y;
            As[c + 2][r] = v.z; As[c + 3][r] = v.w;
        }
        #pragma unroll
        for (int i = tid * 4; i < BN * BK; i += NT * 4) {
            int r = i / BK, c = i % BK;
            float4 v = *(const float4*)(Wb + (size_t)r * K + k0 + c);
            Bs[c + 0][r] = v.x; Bs[c + 1][r] = v.y;
            Bs[c + 2][r] = v.z; Bs[c + 3][r] = v.w;
        }
        __syncthreads();
        #pragma unroll
        for (int k = 0; k < BK; k++) {
            float ra[TM], rb[TN];
            #pragma unroll
            for (int i = 0; i < TM; i++) ra[i] = As[k][tr + i];
            #pragma unroll
            for (int j = 0; j < TN; j++) rb[j] = Bs[k][tc + j];
            #pragma unroll
            for (int i = 0; i < TM; i++)
                #pragma unroll
                for (int j = 0; j < TN; j++)
                    acc[i][j] = fmaf(ra[i], rb[j], acc[i][j]);
        }
        __syncthreads();
    }

    #pragma unroll
    for (int i = 0; i < TM; i++) {
        size_t rowo = (size_t)(crow + tr + i) * Nn;
        #pragma unroll
        for (int j = 0; j < TN; j++) {
            int n = ccol + tc + j;
            float v = acc[i][j];
            if (EPI == EPI_SOFTPLUS) {
                v += bias[n];
                v = (v > 20.f) ? v : log1pf(__expf(v));
            } else if (EPI == EPI_GELU_RES) {
                v += bias[n];
                float g = 0.5f * v * (1.f + erff(v * 0.70710678118654752f));
                v = g + res[rowo + n];
            }
            C[rowo + n] = v;
        }
    }
}

// ---------------------------------------------------------------------------
// Depthwise causal conv (D_CONV=4) + bias + SiLU.
// Input is the first DI columns of g_xz (row stride 2*DI).
// ---------------------------------------------------------------------------
__global__ void conv_silu(const float* __restrict__ xz,
                          const float* __restrict__ cw,
                          const float* __restrict__ cb,
                          float* __restrict__ xc)
{
    int idx = blockIdx.x * 256 + threadIdx.x;
    if (idx >= M_ * DI) return;
    int d  = idx % DI;
    int ml = idx / DI;
    int l  = ml & (L_ - 1);
    const float* base = xz + (size_t)ml * (2 * DI) + d;
    float w0 = cw[d * 4 + 0], w1 = cw[d * 4 + 1];
    float w2 = cw[d * 4 + 2], w3 = cw[d * 4 + 3];
    float acc = cb[d] + w3 * base[0];
    if (l >= 1) acc += w2 * base[-(ptrdiff_t)(2 * DI)];
    if (l >= 2) acc += w1 * base[-(ptrdiff_t)(4 * DI)];
    if (l >= 3) acc += w0 * base[-(ptrdiff_t)(6 * DI)];
    xc[idx] = acc / (1.f + __expf(-acc));   // silu
}

// Zero-pad x_proj weight from 80 rows to 128 rows (row length DI).
__global__ void pad_w(const float* __restrict__ xpw, float* __restrict__ wp)
{
    int idx = blockIdx.x * 256 + threadIdx.x;
    if (idx >= XLD * DI) return;
    int nrow = idx / DI;
    wp[idx] = (nrow < 80) ? xpw[idx] : 0.f;
}

// ---------------------------------------------------------------------------
// Selective scan. 16 lanes per channel (B*DI = 3072 channels, 2 per warp).
// h[n]_{l} = exp(dt*A[n]) * h[n]_{l-1} + dt*xc*B[l,n];  y_l = sum_n h[n]*C[l,n]
// then y = (y + xc*D) * silu(z)  written to yg.
// ---------------------------------------------------------------------------
__global__ void scan_kernel(const float* __restrict__ dt,
                            const float* __restrict__ xc,
                            const float* __restrict__ xdbl,
                            const float* __restrict__ xz,
                            const float* __restrict__ A_log,
                            const float* __restrict__ Dp,
                            float* __restrict__ yg)
{
    int w    = blockIdx.x * 8 + (threadIdx.x >> 5);
    int lane = threadIdx.x & 31;
    int c    = 2 * w + (lane >> 4);          // channel in [0, B*DI)
    int n    = lane & 15;                    // state index
    int b    = c / DI;
    int d    = c - b * DI;

    float An = -__expf(A_log[d * DS + n]);
    float Dv = Dp[d];
    float h  = 0.f;
    int base = b * L_;

    for (int l = 0; l < L_; l++) {
        int row = base + l;
        float dtv = __ldg(dt   + (size_t)row * DI  + d);
        float xcv = __ldg(xc   + (size_t)row * DI  + d);
        float Bv  = __ldg(xdbl + (size_t)row * XLD + 48 + n);
        float Cv  = __ldg(xdbl + (size_t)row * XLD + 64 + n);
        float dA  = __expf(dtv * An);
        h = fmaf(dA, h, dtv * xcv * Bv);
        float p = h * Cv;
        p += __shfl_xor_sync(0xffffffffu, p, 8);
        p += __shfl_xor_sync(0xffffffffu, p, 4);
        p += __shfl_xor_sync(0xffffffffu, p, 2);
        p += __shfl_xor_sync(0xffffffffu, p, 1);
        if (n == 0) {
            float y = p + xcv * Dv;
            float z = xz[(size_t)row * (2 * DI) + DI + d];
            y *= z / (1.f + __expf(-z));     // * silu(z)
            yg[(size_t)row * DI + d] = y;
        }
    }
}

// x2 = x + y_fwd + flip_L(y_bwd)
__global__ void combine_kernel(const float* __restrict__ x,
                               const float* __restrict__ yf,
                               const float* __restrict__ yb,
                               float* __restrict__ x2)
{
    int idx = blockIdx.x * 256 + threadIdx.x;
    if (idx >= M_ * DM) return;
    int j  = idx % DM;
    int ml = idx / DM;
    int l  = ml & (L_ - 1);
    int b  = ml >> 10;
    int mlr = (b << 10) + (L_ - 1 - l);
    x2[idx] = x[idx] + yf[idx] + yb[(size_t)mlr * DM + j];
}

// ---------------------------------------------------------------------------
// Launch
// ---------------------------------------------------------------------------
extern "C" void kernel_launch(void* const* d_in, const int* in_sizes, int n_in,
                              void* d_out, int out_size)
{
    const float* x    = (const float*)d_in[0];
    const float* ln1w = (const float*)d_in[1];
    const float* ln1b = (const float*)d_in[2];
    const float* ln2w = (const float*)d_in[3];
    const float* ln2b = (const float*)d_in[4];
    const float* fcw  = (const float*)d_in[5];
    const float* fcb  = (const float*)d_in[6];

    float *xn, *xnrev, *xz, *xcb, *xdbl, *dtb, *ygb, *yf, *yb, *x2, *xn2, *wp;
    cudaGetSymbolAddress((void**)&xn,    g_xn);
    cudaGetSymbolAddress((void**)&xnrev, g_xnrev);
    cudaGetSymbolAddress((void**)&xz,    g_xz);
    cudaGetSymbolAddress((void**)&xcb,   g_xc);
    cudaGetSymbolAddress((void**)&xdbl,  g_xdbl);
    cudaGetSymbolAddress((void**)&dtb,   g_dt);
    cudaGetSymbolAddress((void**)&ygb,   g_yg);
    cudaGetSymbolAddress((void**)&yf,    g_yf);
    cudaGetSymbolAddress((void**)&yb,    g_yb);
    cudaGetSymbolAddress((void**)&x2,    g_x2);
    cudaGetSymbolAddress((void**)&xn2,   g_xn2);
    cudaGetSymbolAddress((void**)&wp,    g_wxp);

    // 1) LN1 (also produces the L-flipped copy for the backward branch)
    ln_kernel<<<M_, 256>>>(x, ln1w, ln1b, xn, xnrev);

    for (int dir = 0; dir < 2; dir++) {
        const float* Ain  = dir ? xnrev : xn;
        int o = 7 + dir * 9;
        const float* ipw  = (const float*)d_in[o + 0];   // in_proj_w  (3072,768)
        const float* cw   = (const float*)d_in[o + 1];   // conv_w     (1536,4)
        const float* cb   = (const float*)d_in[o + 2];   // conv_b     (1536)
        const float* xpw  = (const float*)d_in[o + 3];   // x_proj_w   (80,1536)
        const float* dpw  = (const float*)d_in[o + 4];   // dt_proj_w  (1536,48)
        const float* dpb  = (const float*)d_in[o + 5];   // dt_proj_b  (1536)
        const float* alog = (const float*)d_in[o + 6];   // A_log      (1536,16)
        const float* Dpar = (const float*)d_in[o + 7];   // D          (1536)
        const float* opw  = (const float*)d_in[o + 8];   // out_proj_w (768,1536)
        float* ydir = dir ? yb : yf;

        // in_proj: xz = xn @ ipw^T   [2048 x 3072]
        sgemm<128, 128, 8, 8, 8, EPI_NONE>
            <<<dim3((2 * DI) / 128, M_ / 128), 256>>>(
                M_, 2 * DI, DM, DM, Ain, ipw, nullptr, nullptr, xz);

        // depthwise causal conv + bias + silu -> xc
        conv_silu<<<(M_ * DI + 255) / 256, 256>>>(xz, cw, cb, xcb);

        // pad x_proj weight to 128 rows, then x_dbl = xc @ wp^T [2048 x 128]
        pad_w<<<(XLD * DI + 255) / 256, 256>>>(xpw, wp);
        sgemm<64, 64, 16, 4, 4, EPI_NONE>
            <<<dim3(XLD / 64, M_ / 64), 256>>>(
                M_, XLD, DI, DI, xcb, wp, nullptr, nullptr, xdbl);

        // dt = softplus(x_dbl[:, :48] @ dpw^T + dpb)   [2048 x 1536]
        sgemm<128, 128, 8, 8, 8, EPI_SOFTPLUS>
            <<<dim3(DI / 128, M_ / 128), 256>>>(
                M_, DI, DTR, XLD, xdbl, dpw, dpb, nullptr, dtb);

        // selective scan + skip (xc*D) + gate silu(z)
        scan_kernel<<<192, 256>>>(dtb, xcb, xdbl, xz, alog, Dpar, ygb);

        // out_proj: ydir = yg @ opw^T  [2048 x 768]
        sgemm<64, 128, 16, 4, 8, EPI_NONE>
            <<<dim3(DM / 128, M_ / 64), 256>>>(
                M_, DM, DI, DI, ygb, opw, nullptr, nullptr, ydir);
    }

    // x2 = x + y_f + flip(y_b); LN2; out = gelu(LN2(x2) @ fcw^T + fcb) + x2
    combine_kernel<<<(M_ * DM + 255) / 256, 256>>>(x, yf, yb, x2);
    ln_kernel<<<M_, 256>>>(x2, ln2w, ln2b, xn2, nullptr);
    sgemm<64, 128, 16, 4, 8, EPI_GELU_RES>
        <<<dim3(DM / 128, M_ / 64), 256>>>(
            M_, DM, DM, DM, xn2, fcw, fcb, x2, (float*)d_out);
}